// round 2
// baseline (speedup 1.0000x reference)
#include <cuda_runtime.h>
#include <cstdint>
#include <cstddef>

// Problem constants (shapes fixed by the dataset; N/E re-derived at launch).
#define NMAX 100000
#define DIMX 64
#define HEADS 4
#define DQK 8
#define DHX 32          // HEADS*DQK
#define VDX 16          // DIMX/HEADS
#define RPE 18
#define QKV_OUT 128     // 2*DHX + DIMX
#define WSTRIDE 22      // padded smem row stride in float2 (176B: 16B-aligned rows)

// Scratch (allocation-free contract: __device__ globals)
__device__ float g_nodes[(size_t)NMAX * 128];  // [q*scale(32) | k(32) | v(64)] per node
__device__ float g_den[(size_t)NMAX * 4];      // softmax denominators per (node, head)

typedef unsigned long long ull;

// ---- packed fp32x2 helpers (Blackwell) ----
__device__ __forceinline__ ull pack2(float lo, float hi) {
    ull r; asm("mov.b64 %0, {%1,%2};" : "=l"(r) : "f"(lo), "f"(hi)); return r;
}
__device__ __forceinline__ float2 unpack2(ull v) {
    float2 f; asm("mov.b64 {%0,%1}, %2;" : "=f"(f.x), "=f"(f.y) : "l"(v)); return f;
}
__device__ __forceinline__ ull fma2(ull a, ull b, ull c) {
    ull d; asm("fma.rn.f32x2 %0, %1, %2, %3;" : "=l"(d) : "l"(a), "l"(b), "l"(c)); return d;
}
__device__ __forceinline__ ull add2(ull a, ull b) {
    ull d; asm("add.rn.f32x2 %0, %1, %2;" : "=l"(d) : "l"(a), "l"(b)); return d;
}
__device__ __forceinline__ ull mul2(ull a, ull b) {
    ull d; asm("mul.rn.f32x2 %0, %1, %2;" : "=l"(d) : "l"(a), "l"(b)); return d;
}
// vectorized global reduction (sm_90+)
__device__ __forceinline__ void red_add_v4(float* addr, float4 v) {
    asm volatile("red.global.add.v4.f32 [%0], {%1,%2,%3,%4};"
                 :: "l"(addr), "f"(v.x), "f"(v.y), "f"(v.z), "f"(v.w) : "memory");
}

// ---------------------------------------------------------------------------
// Kernel 0: zero output accumulators + denominators
// ---------------------------------------------------------------------------
__global__ void zero_kernel(float* __restrict__ out, int n_out, int n_den) {
    int idx = blockIdx.x * blockDim.x + threadIdx.x;
    int stride = gridDim.x * blockDim.x;
    for (int i = idx; i < n_out; i += stride) out[i] = 0.0f;
    for (int i = idx; i < n_den; i += stride) g_den[i] = 0.0f;
}

// ---------------------------------------------------------------------------
// Kernel 1: node QKV projection.  128 threads/block, 16 nodes/block.
// Thread o computes output column o for all 16 nodes (register-blocked).
// q columns (o<32) are pre-scaled by D^-0.5.
// ---------------------------------------------------------------------------
#define QKV_NODES 16
__global__ __launch_bounds__(128) void qkv_kernel(
    const float* __restrict__ x, const float* __restrict__ W,
    const float* __restrict__ b, int N_) {
    __shared__ __align__(16) float xs[DIMX][QKV_NODES];  // transposed tile
    int tid = threadIdx.x;
    int nb = blockIdx.x * QKV_NODES;

    for (int m = tid; m < DIMX * QKV_NODES; m += 128) {
        int nn = m / DIMX, i = m % DIMX;
        int n = nb + nn;
        xs[i][nn] = (n < N_) ? x[(size_t)n * DIMX + i] : 0.0f;
    }
    __syncthreads();

    int o = tid;  // 0..127
    float bo = b[o];
    float acc[QKV_NODES];
#pragma unroll
    for (int nn = 0; nn < QKV_NODES; nn++) acc[nn] = bo;

#pragma unroll 4
    for (int i = 0; i < DIMX; i++) {
        float w = __ldg(&W[i * QKV_OUT + o]);
        const float4* xp = reinterpret_cast<const float4*>(&xs[i][0]);
#pragma unroll
        for (int q4 = 0; q4 < QKV_NODES / 4; q4++) {
            float4 xv = xp[q4];
            acc[q4 * 4 + 0] = fmaf(xv.x, w, acc[q4 * 4 + 0]);
            acc[q4 * 4 + 1] = fmaf(xv.y, w, acc[q4 * 4 + 1]);
            acc[q4 * 4 + 2] = fmaf(xv.z, w, acc[q4 * 4 + 2]);
            acc[q4 * 4 + 3] = fmaf(xv.w, w, acc[q4 * 4 + 3]);
        }
    }
    float mult = (o < DHX) ? 0.35355339059327373f : 1.0f;  // scale q only
#pragma unroll
    for (int nn = 0; nn < QKV_NODES; nn++) {
        int n = nb + nn;
        if (n < N_) g_nodes[(size_t)n * 128 + o] = acc[nn] * mult;
    }
}

// ---------------------------------------------------------------------------
// Kernel 2: edge pass.  4 lanes per edge (one per head).
// Per lane: RPE projections via packed fp32x2 FMA, compat dot, exp, and
// scatter (denominator RED.32, message 4x RED.v4.128).
// ---------------------------------------------------------------------------
#define ETPB 256
#define EDGES_PER_BLK (ETPB / 4)
__global__ __launch_bounds__(ETPB) void edge_kernel(
    const int* __restrict__ ei, const float* __restrict__ ea,
    const float* __restrict__ q_rpe_w, const float* __restrict__ q_rpe_b,
    const float* __restrict__ k_rpe_w, const float* __restrict__ k_rpe_b,
    const float* __restrict__ v_rpe_w, const float* __restrict__ v_rpe_b,
    float* __restrict__ out, int E_) {
    // weights pre-packed as f32x2 column pairs: row p (= col/2), padded stride
    // WSTRIDE float2 per row so every row base is 16B-aligned (LDS.128-safe).
    __shared__ __align__(16) float2 sWq[16 * WSTRIDE];
    __shared__ __align__(16) float2 sWk[16 * WSTRIDE];
    __shared__ __align__(16) float2 sWv[32 * WSTRIDE];
    __shared__ __align__(16) float2 sbq[16];
    __shared__ __align__(16) float2 sbk[16];
    __shared__ __align__(16) float2 sbv[32];

    int tid = threadIdx.x;
    for (int m = tid; m < 16 * RPE; m += ETPB) {
        int p = m / RPE, j = m % RPE;
        sWq[p * WSTRIDE + j] = make_float2(q_rpe_w[j * DHX + 2 * p], q_rpe_w[j * DHX + 2 * p + 1]);
        sWk[p * WSTRIDE + j] = make_float2(k_rpe_w[j * DHX + 2 * p], k_rpe_w[j * DHX + 2 * p + 1]);
    }
    for (int m = tid; m < 32 * RPE; m += ETPB) {
        int p = m / RPE, j = m % RPE;
        sWv[p * WSTRIDE + j] = make_float2(v_rpe_w[j * DIMX + 2 * p], v_rpe_w[j * DIMX + 2 * p + 1]);
    }
    if (tid < 16) {
        sbq[tid] = make_float2(q_rpe_b[2 * tid], q_rpe_b[2 * tid + 1]);
        sbk[tid] = make_float2(k_rpe_b[2 * tid], k_rpe_b[2 * tid + 1]);
    }
    if (tid < 32) {
        sbv[tid] = make_float2(v_rpe_b[2 * tid], v_rpe_b[2 * tid + 1]);
    }
    __syncthreads();

    int e = blockIdx.x * EDGES_PER_BLK + (tid >> 2);
    if (e >= E_) return;
    int h = tid & 3;

    int s = ei[e];
    int t = ei[(size_t)E_ + e];

    // edge_attr row: 18 floats = 9 float2 (8B aligned), packed into (a,a) pairs
    ull a2[RPE];
    const float2* eap = reinterpret_cast<const float2*>(ea + (size_t)e * RPE);
#pragma unroll
    for (int jj = 0; jj < 9; jj++) {
        float2 v = __ldg(&eap[jj]);
        a2[2 * jj]     = pack2(v.x, v.x);
        a2[2 * jj + 1] = pack2(v.y, v.y);
    }

    const float* nodeS = g_nodes + (size_t)s * 128;
    const float* nodeT = g_nodes + (size_t)t * 128;

    // ---- compat for this head ----
    float compat = 0.0f;
#pragma unroll
    for (int pp = 0; pp < 4; pp++) {
        int p = h * 4 + pp;  // d-pair index; hd = 2p
        ull qr = *reinterpret_cast<const ull*>(&sbq[p]);
        ull kr = *reinterpret_cast<const ull*>(&sbk[p]);
        const ulonglong2* wq = reinterpret_cast<const ulonglong2*>(sWq + p * WSTRIDE);
        const ulonglong2* wk = reinterpret_cast<const ulonglong2*>(sWk + p * WSTRIDE);
#pragma unroll
        for (int jj = 0; jj < 9; jj++) {
            ulonglong2 w1 = wq[jj];
            ulonglong2 w2 = wk[jj];
            qr = fma2(a2[2 * jj], w1.x, qr);
            qr = fma2(a2[2 * jj + 1], w1.y, qr);
            kr = fma2(a2[2 * jj], w2.x, kr);
            kr = fma2(a2[2 * jj + 1], w2.y, kr);
        }
        float2 qg = *reinterpret_cast<const float2*>(nodeS + 2 * p);        // q (pre-scaled)
        float2 kg = *reinterpret_cast<const float2*>(nodeT + DHX + 2 * p);  // k
        float2 qe = unpack2(qr);
        float2 ke = unpack2(kr);
        qe.x += qg.x; qe.y += qg.y;
        ke.x += kg.x; ke.y += kg.y;
        compat = fmaf(qe.x, ke.x, compat);
        compat = fmaf(qe.y, ke.y, compat);
    }

    // softmax numerator; denominator factored out (divided in norm_kernel)
    float ex = __expf(compat);
    atomicAdd(&g_den[(size_t)s * 4 + h], ex);  // RED.32 (return value unused)

    ull ex2 = pack2(ex, ex);
    // ---- message: (v[t] + v_rpe) * ex, scattered with vec4 reductions ----
#pragma unroll
    for (int g4 = 0; g4 < 4; g4++) {
        float4 m4;
        float* mp = &m4.x;
#pragma unroll
        for (int half = 0; half < 2; half++) {
            int vp = h * 8 + g4 * 2 + half;  // v-pair index; i = 2*vp
            ull vr = *reinterpret_cast<const ull*>(&sbv[vp]);
            const ulonglong2* wv = reinterpret_cast<const ulonglong2*>(sWv + vp * WSTRIDE);
#pragma unroll
            for (int jj = 0; jj < 9; jj++) {
                ulonglong2 w = wv[jj];
                vr = fma2(a2[2 * jj], w.x, vr);
                vr = fma2(a2[2 * jj + 1], w.y, vr);
            }
            float2 vg = *reinterpret_cast<const float2*>(nodeT + 2 * DHX + 2 * vp);
            ull msum = add2(vr, pack2(vg.x, vg.y));
            ull m2 = mul2(msum, ex2);
            float2 mf = unpack2(m2);
            mp[half * 2]     = mf.x;
            mp[half * 2 + 1] = mf.y;
        }
        red_add_v4(out + (size_t)s * DIMX + h * VDX + g4 * 4, m4);
    }
}

// ---------------------------------------------------------------------------
// Kernel 3: divide by softmax denominator
// ---------------------------------------------------------------------------
__global__ void norm_kernel(float* __restrict__ out, int N_) {
    int idx = blockIdx.x * blockDim.x + threadIdx.x;
    int total = N_ * DIMX;
    if (idx < total) {
        int n = idx >> 6;
        int i = idx & 63;
        out[idx] = out[idx] / (g_den[(size_t)n * 4 + (i >> 4)] + 1e-16f);
    }
}

// ---------------------------------------------------------------------------
extern "C" void kernel_launch(void* const* d_in, const int* in_sizes, int n_in,
                              void* d_out, int out_size) {
    const float* x        = (const float*)d_in[0];
    const int* ei         = (const int*)d_in[1];   // int32 (JAX canonicalizes int64->int32)
    const float* ea       = (const float*)d_in[2];
    const float* qkv_w    = (const float*)d_in[3];
    const float* qkv_b    = (const float*)d_in[4];
    const float* k_rpe_w  = (const float*)d_in[5];
    const float* k_rpe_b  = (const float*)d_in[6];
    const float* q_rpe_w  = (const float*)d_in[7];
    const float* q_rpe_b  = (const float*)d_in[8];
    const float* v_rpe_w  = (const float*)d_in[9];
    const float* v_rpe_b  = (const float*)d_in[10];
    float* out = (float*)d_out;

    int N_ = in_sizes[0] / DIMX;
    int E_ = in_sizes[2] / RPE;

    zero_kernel<<<512, 256>>>(out, N_ * DIMX, N_ * HEADS);
    qkv_kernel<<<(N_ + QKV_NODES - 1) / QKV_NODES, 128>>>(x, qkv_w, qkv_b, N_);
    edge_kernel<<<(E_ + EDGES_PER_BLK - 1) / EDGES_PER_BLK, ETPB>>>(
        ei, ea, q_rpe_w, q_rpe_b, k_rpe_w, k_rpe_b, v_rpe_w, v_rpe_b, out, E_);
    norm_kernel<<<(N_ * DIMX + 255) / 256, 256>>>(out, N_);
}

// round 3
// speedup vs baseline: 3.1306x; 3.1306x over previous
#include <cuda_runtime.h>
#include <cstdint>
#include <cstddef>

#define NMAX 100000
#define DIMX 64
#define HEADS 4
#define DHX 32
#define VDX 16
#define RPE 18
#define QKV_OUT 128

// Scratch (allocation-free contract)
__device__ float g_nodes[(size_t)NMAX * 128];  // [q*scale(32) | k(32) | v(64)]
__device__ float g_den[(size_t)NMAX * 4];

typedef unsigned long long ull;

__device__ __forceinline__ ull pack2(float lo, float hi) {
    ull r; asm("mov.b64 %0, {%1,%2};" : "=l"(r) : "f"(lo), "f"(hi)); return r;
}
__device__ __forceinline__ ull fma2(ull a, ull b, ull c) {
    ull d; asm("fma.rn.f32x2 %0, %1, %2, %3;" : "=l"(d) : "l"(a), "l"(b), "l"(c)); return d;
}
__device__ __forceinline__ void red_add_v4(float* addr, float4 v) {
    asm volatile("red.global.add.v4.f32 [%0], {%1,%2,%3,%4};"
                 :: "l"(addr), "f"(v.x), "f"(v.y), "f"(v.z), "f"(v.w) : "memory");
}
__device__ __forceinline__ void sts64(void* addr, ull v) {
    asm volatile("st.shared.b64 [%0], %1;" :: "l"(__cvta_generic_to_shared(addr)), "l"(v) : "memory");
}

// ---------------------------------------------------------------------------
__global__ void zero_kernel(float* __restrict__ out, int n_out, int n_den) {
    int idx = blockIdx.x * blockDim.x + threadIdx.x;
    int stride = gridDim.x * blockDim.x;
    for (int i = idx; i < n_out; i += stride) out[i] = 0.0f;
    for (int i = idx; i < n_den; i += stride) g_den[i] = 0.0f;
}

// ---------------------------------------------------------------------------
#define QKV_NODES 16
__global__ __launch_bounds__(128) void qkv_kernel(
    const float* __restrict__ x, const float* __restrict__ W,
    const float* __restrict__ b, int N_) {
    __shared__ __align__(16) float xs[DIMX][QKV_NODES];
    int tid = threadIdx.x;
    int nb = blockIdx.x * QKV_NODES;

    for (int m = tid; m < DIMX * QKV_NODES; m += 128) {
        int nn = m / DIMX, i = m % DIMX;
        int n = nb + nn;
        xs[i][nn] = (n < N_) ? x[(size_t)n * DIMX + i] : 0.0f;
    }
    __syncthreads();

    int o = tid;
    float bo = b[o];
    float acc[QKV_NODES];
#pragma unroll
    for (int nn = 0; nn < QKV_NODES; nn++) acc[nn] = bo;

#pragma unroll 4
    for (int i = 0; i < DIMX; i++) {
        float w = __ldg(&W[i * QKV_OUT + o]);
        const float4* xp = reinterpret_cast<const float4*>(&xs[i][0]);
#pragma unroll
        for (int q4 = 0; q4 < QKV_NODES / 4; q4++) {
            float4 xv = xp[q4];
            acc[q4 * 4 + 0] = fmaf(xv.x, w, acc[q4 * 4 + 0]);
            acc[q4 * 4 + 1] = fmaf(xv.y, w, acc[q4 * 4 + 1]);
            acc[q4 * 4 + 2] = fmaf(xv.z, w, acc[q4 * 4 + 2]);
            acc[q4 * 4 + 3] = fmaf(xv.w, w, acc[q4 * 4 + 3]);
        }
    }
    float mult = (o < DHX) ? 0.35355339059327373f : 1.0f;
#pragma unroll
    for (int nn = 0; nn < QKV_NODES; nn++) {
        int n = nb + nn;
        if (n < N_) g_nodes[(size_t)n * 128 + o] = acc[nn] * mult;
    }
}

// ---------------------------------------------------------------------------
// Edge kernel: 128 threads, 32 edges per block, two phases.
//  Phase 1: RPE GEMM  (32 x 18) @ (18 x 128)  -> rpe_sm tile
//           thread (eg, cg): 8 edges x 4 cols, weights/attr amortized via smem
//  Phase 2: thread (e_loc, h): gather q/k/v, compat, exp, RED scatter
// ---------------------------------------------------------------------------
#define EB 32           // edges per block
#define RPR 132         // rpe_sm row stride (floats): 528B, 16B-aligned, bank-rotated
#define ARS 36          // a_sm row stride (floats)

__global__ __launch_bounds__(128, 6) void edge_kernel(
    const int* __restrict__ ei, const float* __restrict__ ea,
    const float* __restrict__ q_rpe_w, const float* __restrict__ q_rpe_b,
    const float* __restrict__ k_rpe_w, const float* __restrict__ k_rpe_b,
    const float* __restrict__ v_rpe_w, const float* __restrict__ v_rpe_b,
    float* __restrict__ out, int E_) {
    __shared__ __align__(16) float w_sm[RPE][128];     // combined [Wq|Wk|Wv] rows
    __shared__ __align__(16) float bias_sm[128];
    __shared__ __align__(16) float a_sm[RPE][ARS];     // edge_attr transposed
    __shared__ __align__(16) float rpe_sm[EB][RPR];    // per-edge RPE outputs

    int tid = threadIdx.x;
    int e0 = blockIdx.x * EB;

    // ---- stage weights (coalesced: thread = col, iterate j) ----
    {
        int c = tid;
        const float* src;
        int cc;
        if (c < 32)      { src = q_rpe_w; cc = c; }
        else if (c < 64) { src = k_rpe_w; cc = c - 32; }
        else             { src = v_rpe_w; cc = c - 64; }
        int stride = (c < 64) ? 32 : 64;
#pragma unroll
        for (int j = 0; j < RPE; j++) w_sm[j][c] = __ldg(&src[j * stride + cc]);
        bias_sm[c] = (c < 32) ? __ldg(&q_rpe_b[c])
                   : (c < 64) ? __ldg(&k_rpe_b[c - 32])
                              : __ldg(&v_rpe_b[c - 64]);
    }
    // ---- stage edge_attr transposed ----
    for (int i = tid; i < EB * RPE; i += 128) {
        int el = i / RPE, j = i % RPE;
        int e = e0 + el;
        a_sm[j][el] = (e < E_) ? __ldg(&ea[(size_t)e * RPE + j]) : 0.0f;
    }
    __syncthreads();

    // ---- Phase 1: GEMM.  cg = col group (4 cols), eg = edge group (8 edges) ----
    {
        int cg = tid & 31;        // 0..31 -> cols cg*4..cg*4+3
        int eg = tid >> 5;        // 0..3  -> edges eg*8..eg*8+7
        const float4* w4row;
        float4 b4 = reinterpret_cast<const float4*>(bias_sm)[cg];
        ull bias01 = pack2(b4.x, b4.y);
        ull bias23 = pack2(b4.z, b4.w);
        ull acc0[8], acc1[8];
#pragma unroll
        for (int ee = 0; ee < 8; ee++) { acc0[ee] = bias01; acc1[ee] = bias23; }

#pragma unroll
        for (int j = 0; j < RPE; j++) {
            float4 w4 = reinterpret_cast<const float4*>(&w_sm[j][0])[cg];
            ull w01 = pack2(w4.x, w4.y);
            ull w23 = pack2(w4.z, w4.w);
            // 8 edges of attr (warp-uniform address -> broadcast)
            float4 av0 = reinterpret_cast<const float4*>(&a_sm[j][0])[eg * 2];
            float4 av1 = reinterpret_cast<const float4*>(&a_sm[j][0])[eg * 2 + 1];
            float av[8] = {av0.x, av0.y, av0.z, av0.w, av1.x, av1.y, av1.z, av1.w};
#pragma unroll
            for (int ee = 0; ee < 8; ee++) {
                ull ad = pack2(av[ee], av[ee]);
                acc0[ee] = fma2(ad, w01, acc0[ee]);
                acc1[ee] = fma2(ad, w23, acc1[ee]);
            }
        }
        // store tile: 2 STS.64 per edge
#pragma unroll
        for (int ee = 0; ee < 8; ee++) {
            float* dst = &rpe_sm[eg * 8 + ee][cg * 4];
            sts64(dst, acc0[ee]);
            sts64(dst + 2, acc1[ee]);
        }
    }
    __syncthreads();

    // ---- Phase 2: per (edge, head) ----
    int e_loc = tid >> 2;
    int h = tid & 3;
    int e = e0 + e_loc;
    if (e < E_) {
        int s = ei[e];
        int t = ei[(size_t)E_ + e];
        const float4* nS = reinterpret_cast<const float4*>(g_nodes + (size_t)s * 128);
        const float4* nT = reinterpret_cast<const float4*>(g_nodes + (size_t)t * 128);
        const float4* rp = reinterpret_cast<const float4*>(&rpe_sm[e_loc][0]);

        // compat
        float compat = 0.0f;
#pragma unroll
        for (int qq = 0; qq < 2; qq++) {
            float4 qg = nS[h * 2 + qq];           // q (pre-scaled)
            float4 rq = rp[h * 2 + qq];           // q_rpe
            float4 kg = nT[8 + h * 2 + qq];       // k
            float4 rk = rp[8 + h * 2 + qq];       // k_rpe
            float qx = qg.x + rq.x, qy = qg.y + rq.y, qz = qg.z + rq.z, qw = qg.w + rq.w;
            float kx = kg.x + rk.x, ky = kg.y + rk.y, kz = kg.z + rk.z, kw = kg.w + rk.w;
            compat = fmaf(qx, kx, compat);
            compat = fmaf(qy, ky, compat);
            compat = fmaf(qz, kz, compat);
            compat = fmaf(qw, kw, compat);
        }
        float ex = __expf(compat);
        atomicAdd(&g_den[(size_t)s * 4 + h], ex);

        float* outp = out + (size_t)s * DIMX + h * VDX;
#pragma unroll
        for (int w = 0; w < 4; w++) {
            float4 vg = nT[16 + h * 4 + w];
            float4 rv = rp[16 + h * 4 + w];
            float4 m4;
            m4.x = (vg.x + rv.x) * ex;
            m4.y = (vg.y + rv.y) * ex;
            m4.z = (vg.z + rv.z) * ex;
            m4.w = (vg.w + rv.w) * ex;
            red_add_v4(outp + w * 4, m4);
        }
    }
}

// ---------------------------------------------------------------------------
__global__ void norm_kernel(float* __restrict__ out, int N_) {
    int idx = blockIdx.x * blockDim.x + threadIdx.x;
    int total = N_ * DIMX;
    if (idx < total) {
        int n = idx >> 6;
        int i = idx & 63;
        out[idx] = out[idx] / (g_den[(size_t)n * 4 + (i >> 4)] + 1e-16f);
    }
}

// ---------------------------------------------------------------------------
extern "C" void kernel_launch(void* const* d_in, const int* in_sizes, int n_in,
                              void* d_out, int out_size) {
    const float* x        = (const float*)d_in[0];
    const int* ei         = (const int*)d_in[1];
    const float* ea       = (const float*)d_in[2];
    const float* qkv_w    = (const float*)d_in[3];
    const float* qkv_b    = (const float*)d_in[4];
    const float* k_rpe_w  = (const float*)d_in[5];
    const float* k_rpe_b  = (const float*)d_in[6];
    const float* q_rpe_w  = (const float*)d_in[7];
    const float* q_rpe_b  = (const float*)d_in[8];
    const float* v_rpe_w  = (const float*)d_in[9];
    const float* v_rpe_b  = (const float*)d_in[10];
    float* out = (float*)d_out;

    int N_ = in_sizes[0] / DIMX;
    int E_ = in_sizes[2] / RPE;

    zero_kernel<<<512, 256>>>(out, N_ * DIMX, N_ * HEADS);
    qkv_kernel<<<(N_ + QKV_NODES - 1) / QKV_NODES, 128>>>(x, qkv_w, qkv_b, N_);
    edge_kernel<<<(E_ + EB - 1) / EB, 128>>>(
        ei, ea, q_rpe_w, q_rpe_b, k_rpe_w, k_rpe_b, v_rpe_w, v_rpe_b, out, E_);
    norm_kernel<<<(N_ * DIMX + 255) / 256, 256>>>(out, N_);
}